// round 2
// baseline (speedup 1.0000x reference)
#include <cuda_runtime.h>
#include <math.h>

// Problem constants
#define BB 2
#define TT 256          // t
#define CC 768
#define HH 12
#define DD 64
#define TF 768          // T = 3*t
#define VV 512
#define MC 438
#define NLAYER 6

// Scratch (device globals; no allocations allowed)
__device__ float g_x[(size_t)BB*TF*CC];
__device__ float g_h[(size_t)BB*TF*CC];
__device__ float g_qkv[(size_t)BB*TF*3*CC];
__device__ float g_y[(size_t)BB*TF*CC];
__device__ float g_u[(size_t)BB*TF*4*CC];

// ---------------------------------------------------------------------------
// Generic GEMM: Cout = act(A @ W^T + bias + add), A:[M,K] row-major,
// W:[N,K] row-major. 64x64 block tile, 4x4 per thread, K-tile 16.
// blockIdx.z batches with element strides. M,N must be multiples of 64.
// ---------------------------------------------------------------------------
template<bool GELU>
__global__ void gemm_k(const float* __restrict__ A, long strideA,
                       const float* __restrict__ W,
                       const float* __restrict__ bias,
                       const float* __restrict__ add, long strideAdd,
                       float* __restrict__ Co, long strideC,
                       int M, int N, int K)
{
    __shared__ float As[16][68];
    __shared__ float Bs[16][68];
    const int bz = blockIdx.z;
    A  += (long)bz * strideA;
    if (add) add += (long)bz * strideAdd;
    Co += (long)bz * strideC;

    const int tid = threadIdx.x;          // 256 threads
    const int tx = tid & 15, ty = tid >> 4;
    const int row0 = blockIdx.y << 6, col0 = blockIdx.x << 6;
    const int kk0 = tid & 15, rr0 = tid >> 4;

    float acc[4][4] = {};

    for (int k0 = 0; k0 < K; k0 += 16) {
        const int k = k0 + kk0;
        const bool kin = (k < K);
        #pragma unroll
        for (int r = 0; r < 4; r++) {
            const int rw = rr0 + r * 16;
            As[kk0][rw] = kin ? A[(long)(row0 + rw) * K + k] : 0.f;
            Bs[kk0][rw] = kin ? W[(long)(col0 + rw) * K + k] : 0.f;
        }
        __syncthreads();
        #pragma unroll
        for (int kk = 0; kk < 16; kk++) {
            const float4 av = *(const float4*)&As[kk][ty * 4];
            const float4 bv = *(const float4*)&Bs[kk][tx * 4];
            const float a_[4] = {av.x, av.y, av.z, av.w};
            const float b_[4] = {bv.x, bv.y, bv.z, bv.w};
            #pragma unroll
            for (int i = 0; i < 4; i++)
                #pragma unroll
                for (int j = 0; j < 4; j++)
                    acc[i][j] = fmaf(a_[i], b_[j], acc[i][j]);
        }
        __syncthreads();
    }

    #pragma unroll
    for (int i = 0; i < 4; i++) {
        const long row = row0 + ty * 4 + i;
        const int col = col0 + tx * 4;
        float4 v = make_float4(acc[i][0], acc[i][1], acc[i][2], acc[i][3]);
        if (bias) {
            const float4 bv = *(const float4*)&bias[col];
            v.x += bv.x; v.y += bv.y; v.z += bv.z; v.w += bv.w;
        }
        if (add) {
            const float4 av = *(const float4*)&add[row * N + col];
            v.x += av.x; v.y += av.y; v.z += av.z; v.w += av.w;
        }
        if (GELU) {
            v.x = 0.5f * v.x * (1.f + erff(v.x * 0.70710678118654752f));
            v.y = 0.5f * v.y * (1.f + erff(v.y * 0.70710678118654752f));
            v.z = 0.5f * v.z * (1.f + erff(v.z * 0.70710678118654752f));
            v.w = 0.5f * v.w * (1.f + erff(v.w * 0.70710678118654752f));
        }
        *(float4*)&Co[row * N + col] = v;
    }
}

// ---------------------------------------------------------------------------
// LayerNorm: one block (256 threads) per row of 768.
// ---------------------------------------------------------------------------
__global__ void ln_kernel(const float* __restrict__ x,
                          const float* __restrict__ w,
                          const float* __restrict__ b,
                          float* __restrict__ o)
{
    __shared__ float red[16];
    const long row = blockIdx.x;
    const float* xr = x + row * CC;
    const int tid = threadIdx.x;
    const float v0 = xr[tid], v1 = xr[tid + 256], v2 = xr[tid + 512];
    float s = v0 + v1 + v2;
    float s2 = v0 * v0 + v1 * v1 + v2 * v2;
    #pragma unroll
    for (int off = 16; off; off >>= 1) {
        s  += __shfl_down_sync(0xffffffffu, s,  off);
        s2 += __shfl_down_sync(0xffffffffu, s2, off);
    }
    const int lane = tid & 31, wp = tid >> 5;
    if (!lane) { red[wp] = s; red[wp + 8] = s2; }
    __syncthreads();
    if (tid == 0) {
        float a = 0.f, a2 = 0.f;
        #pragma unroll
        for (int i = 0; i < 8; i++) { a += red[i]; a2 += red[i + 8]; }
        red[0] = a; red[8] = a2;
    }
    __syncthreads();
    const float mu = red[0] * (1.f / 768.f);
    const float var = red[8] * (1.f / 768.f) - mu * mu;
    const float rs = rsqrtf(var + 1e-5f);
    float* orow = o + row * CC;
    orow[tid]       = (v0 - mu) * rs * w[tid]       + b[tid];
    orow[tid + 256] = (v1 - mu) * rs * w[tid + 256] + b[tid + 256];
    orow[tid + 512] = (v2 - mu) * rs * w[tid + 512] + b[tid + 512];
}

// ---------------------------------------------------------------------------
// Attention: one block (128 threads) per (query i, head h, batch b).
// qkv layout: [b*TF + t][k*CC + h*64 + d]. Mask: (j%t) <= (i%t).
// ---------------------------------------------------------------------------
__global__ void attn_kernel(const float* __restrict__ qkv, float* __restrict__ y)
{
    const int i = blockIdx.x, h = blockIdx.y, b = blockIdx.z;
    const int tid = threadIdx.x;
    __shared__ float q[64];
    __shared__ float sc[TF];
    __shared__ float red[8];
    __shared__ float oacc[2][64];

    const float* base = qkv + (long)b * TF * 3 * CC;
    if (tid < 64) q[tid] = base[(long)i * 3 * CC + h * 64 + tid];
    __syncthreads();

    const int im = i & (TT - 1);
    float lmax = -1e30f;
    for (int j = tid; j < TF; j += 128) {
        float s = -1e30f;
        if ((j & (TT - 1)) <= im) {
            const float* kr = base + (long)j * 3 * CC + CC + h * 64;
            float a = 0.f;
            #pragma unroll
            for (int d = 0; d < 64; d += 4) {
                const float4 kv = *(const float4*)(kr + d);
                a = fmaf(q[d], kv.x, fmaf(q[d + 1], kv.y,
                    fmaf(q[d + 2], kv.z, fmaf(q[d + 3], kv.w, a))));
            }
            s = a * 0.125f;   // 1/sqrt(64)
        }
        sc[j] = s;
        lmax = fmaxf(lmax, s);
    }
    #pragma unroll
    for (int o = 16; o; o >>= 1) lmax = fmaxf(lmax, __shfl_down_sync(0xffffffffu, lmax, o));
    const int lane = tid & 31, wp = tid >> 5;
    if (!lane) red[wp] = lmax;
    __syncthreads();
    if (tid == 0) red[0] = fmaxf(fmaxf(red[0], red[1]), fmaxf(red[2], red[3]));
    __syncthreads();
    const float gmax = red[0];

    float lsum = 0.f;
    for (int j = tid; j < TF; j += 128) {
        const float p = __expf(sc[j] - gmax);
        sc[j] = p;
        lsum += p;
    }
    #pragma unroll
    for (int o = 16; o; o >>= 1) lsum += __shfl_down_sync(0xffffffffu, lsum, o);
    __syncthreads();                 // red reuse + sc writes drained
    if (!lane) red[wp] = lsum;
    __syncthreads();
    const float inv = 1.f / (red[0] + red[1] + red[2] + red[3]);

    const int d = tid & 63, half = tid >> 6;
    float a = 0.f;
    for (int j = half; j < TF; j += 2) {
        const float p = sc[j];
        if (p != 0.f)
            a = fmaf(p, base[(long)j * 3 * CC + 2 * CC + h * 64 + d], a);
    }
    oacc[half][d] = a;
    __syncthreads();
    if (tid < 64)
        y[((long)b * TF + i) * CC + h * 64 + d] = (oacc[0][d] + oacc[1][d]) * inv;
}

// ---------------------------------------------------------------------------
// Token embedding segments (up/down) + positional emb.
// ---------------------------------------------------------------------------
__global__ void embed_tok(const int* __restrict__ iu, const int* __restrict__ idn,
                          const float* __restrict__ tu, const float* __restrict__ td,
                          const float* __restrict__ pos, float* __restrict__ x)
{
    const int gid = blockIdx.x * blockDim.x + threadIdx.x;
    const int total = 2 * BB * TT * CC;
    if (gid >= total) return;
    const int c = gid % CC;
    const int rr = gid / CC;
    const int i = rr % TT;
    const int bb = (rr / TT) % BB;
    const int seg = rr / (TT * BB);
    if (seg == 0)
        x[((long)bb * TF + TT + i) * CC + c] =
            tu[(long)iu[bb * TT + i] * CC + c] + pos[(TT + i) * CC + c];
    else
        x[((long)bb * TF + 2 * TT + i) * CC + c] =
            td[(long)idn[bb * TT + i] * CC + c] + pos[(2 * TT + i) * CC + c];
}

// ---------------------------------------------------------------------------
extern "C" void kernel_launch(void* const* d_in, const int* in_sizes, int n_in,
                              void* d_out, int out_size)
{
    (void)n_in; (void)out_size;
    const int*   idx_up   = (const int*)d_in[0];
    const int*   idx_down = (const int*)d_in[1];
    const float* cond     = (const float*)d_in[2];
    const float* tok_up   = (const float*)d_in[3];
    const float* tok_down = (const float*)d_in[4];
    const float* pos_emb  = (const float*)d_in[5];
    const float* cond_w   = (const float*)d_in[6];
    const float* cond_b   = (const float*)d_in[7];

    // Two possible input layouts:
    //  - dict order (setup_inputs insertion): 8..11 = lnf_w, lnf_b, head_up_w,
    //    head_down_w; 12..21 base params; 22..31 head params.
    //  - signature order: 8..17 base params; 18..27 head params; 28..31 finals.
    // Disambiguate via in_sizes[8]: lnf_w has 768 elems, base_ln1 has 9216.
    const bool dict_order = (in_sizes[8] == CC);

    const float* P[2][10];
    const float *lnf_w, *lnf_b, *head_up_w, *head_down_w;
    if (dict_order) {
        lnf_w       = (const float*)d_in[8];
        lnf_b       = (const float*)d_in[9];
        head_up_w   = (const float*)d_in[10];
        head_down_w = (const float*)d_in[11];
        for (int s = 0; s < 2; s++)
            for (int p = 0; p < 10; p++)
                P[s][p] = (const float*)d_in[12 + s * 10 + p];
    } else {
        for (int s = 0; s < 2; s++)
            for (int p = 0; p < 10; p++)
                P[s][p] = (const float*)d_in[8 + s * 10 + p];
        lnf_w       = (const float*)d_in[28];
        lnf_b       = (const float*)d_in[29];
        head_up_w   = (const float*)d_in[30];
        head_down_w = (const float*)d_in[31];
    }
    float* out = (float*)d_out;

    float *x, *h, *qkv, *y, *u;
    cudaGetSymbolAddress((void**)&x,   g_x);
    cudaGetSymbolAddress((void**)&h,   g_h);
    cudaGetSymbolAddress((void**)&qkv, g_qkv);
    cudaGetSymbolAddress((void**)&y,   g_y);
    cudaGetSymbolAddress((void**)&u,   g_u);

    const int NROW = BB * TF;   // 1536

    // Embedding: cond segment via batched GEMM (+pos_emb), token segments gather
    gemm_k<false><<<dim3(CC / 64, TT / 64, BB), 256>>>(
        cond, (long)TT * MC, cond_w, cond_b, pos_emb, 0,
        x, (long)TF * CC, TT, CC, MC);
    embed_tok<<<(2 * BB * TT * CC + 255) / 256, 256>>>(
        idx_up, idx_down, tok_up, tok_down, pos_emb, x);

    for (int s = 0; s < 2; s++) {
        for (int l = 0; l < NLAYER; l++) {
            const float* ln1  = P[s][0] + (long)l * 2 * CC;
            const float* ln2  = P[s][1] + (long)l * 2 * CC;
            const float* qkvW = P[s][2] + (long)l * 3 * CC * CC;
            const float* qkvB = P[s][3] + (long)l * 3 * CC;
            const float* prjW = P[s][4] + (long)l * CC * CC;
            const float* prjB = P[s][5] + (long)l * CC;
            const float* f1W  = P[s][6] + (long)l * 4 * CC * CC;
            const float* f1B  = P[s][7] + (long)l * 4 * CC;
            const float* f2W  = P[s][8] + (long)l * CC * 4 * CC;
            const float* f2B  = P[s][9] + (long)l * CC;

            ln_kernel<<<NROW, 256>>>(x, ln1, ln1 + CC, h);
            gemm_k<false><<<dim3(3 * CC / 64, NROW / 64, 1), 256>>>(
                h, 0, qkvW, qkvB, nullptr, 0, qkv, 0, NROW, 3 * CC, CC);
            attn_kernel<<<dim3(TF, HH, BB), 128>>>(qkv, y);
            gemm_k<false><<<dim3(CC / 64, NROW / 64, 1), 256>>>(
                y, 0, prjW, prjB, x, 0, x, 0, NROW, CC, CC);
            ln_kernel<<<NROW, 256>>>(x, ln2, ln2 + CC, h);
            gemm_k<true><<<dim3(4 * CC / 64, NROW / 64, 1), 256>>>(
                h, 0, f1W, f1B, nullptr, 0, u, 0, NROW, 4 * CC, CC);
            gemm_k<false><<<dim3(CC / 64, NROW / 64, 1), 256>>>(
                u, 0, f2W, f2B, x, 0, x, 0, NROW, CC, 4 * CC);
        }
    }

    // Final LN + heads
    ln_kernel<<<NROW, 256>>>(x, lnf_w, lnf_b, h);
    gemm_k<false><<<dim3(VV / 64, TT / 64, BB), 256>>>(
        h + (long)TT * CC, (long)TF * CC, head_up_w, nullptr, nullptr, 0,
        out, (long)TT * VV, TT, VV, CC);
    gemm_k<false><<<dim3(VV / 64, TT / 64, BB), 256>>>(
        h + (long)2 * TT * CC, (long)TF * CC, head_down_w, nullptr, nullptr, 0,
        out + (long)BB * TT * VV, (long)TT * VV, TT, VV, CC);
}

// round 6
// speedup vs baseline: 1.5894x; 1.5894x over previous
#include <cuda_runtime.h>
#include <math.h>

// Problem constants
#define BB 2
#define TT 256          // t
#define CC 768
#define HH 12
#define DD 64
#define TF 768          // T = 3*t
#define VV 512
#define MC 438
#define NLAYER 6

// Scratch (device globals; no allocations allowed)
__device__ float g_x[(size_t)BB*TF*CC];
__device__ float g_h[(size_t)BB*TF*CC];
__device__ float g_qkv[(size_t)BB*TF*3*CC];
__device__ float g_y[(size_t)BB*TF*CC];
__device__ float g_u[(size_t)BB*TF*4*CC];

// ---------------------------------------------------------------------------
// Generic GEMM: Cout = act(A @ W^T + bias + add), A:[M,K] row-major,
// W:[N,K] row-major. 64x64 block tile, 4x4 per thread, K-tile 16.
// ---------------------------------------------------------------------------
template<bool GELU>
__global__ void gemm_k(const float* __restrict__ A, long strideA,
                       const float* __restrict__ W,
                       const float* __restrict__ bias,
                       const float* __restrict__ add, long strideAdd,
                       float* __restrict__ Co, long strideC,
                       int M, int N, int K)
{
    __shared__ float As[16][68];
    __shared__ float Bs[16][68];
    const int bz = blockIdx.z;
    A  += (long)bz * strideA;
    if (add) add += (long)bz * strideAdd;
    Co += (long)bz * strideC;

    const int tid = threadIdx.x;          // 256 threads
    const int tx = tid & 15, ty = tid >> 4;
    const int row0 = blockIdx.y << 6, col0 = blockIdx.x << 6;
    const int kk0 = tid & 15, rr0 = tid >> 4;

    float acc[4][4] = {};

    for (int k0 = 0; k0 < K; k0 += 16) {
        const int k = k0 + kk0;
        const bool kin = (k < K);
        #pragma unroll
        for (int r = 0; r < 4; r++) {
            const int rw = rr0 + r * 16;
            As[kk0][rw] = kin ? A[(long)(row0 + rw) * K + k] : 0.f;
            Bs[kk0][rw] = kin ? W[(long)(col0 + rw) * K + k] : 0.f;
        }
        __syncthreads();
        #pragma unroll
        for (int kk = 0; kk < 16; kk++) {
            const float4 av = *(const float4*)&As[kk][ty * 4];
            const float4 bv = *(const float4*)&Bs[kk][tx * 4];
            const float a_[4] = {av.x, av.y, av.z, av.w};
            const float b_[4] = {bv.x, bv.y, bv.z, bv.w};
            #pragma unroll
            for (int i = 0; i < 4; i++)
                #pragma unroll
                for (int j = 0; j < 4; j++)
                    acc[i][j] = fmaf(a_[i], b_[j], acc[i][j]);
        }
        __syncthreads();
    }

    #pragma unroll
    for (int i = 0; i < 4; i++) {
        const long row = row0 + ty * 4 + i;
        const int col = col0 + tx * 4;
        float4 v = make_float4(acc[i][0], acc[i][1], acc[i][2], acc[i][3]);
        if (bias) {
            const float4 bv = *(const float4*)&bias[col];
            v.x += bv.x; v.y += bv.y; v.z += bv.z; v.w += bv.w;
        }
        if (add) {
            const float4 av = *(const float4*)&add[row * N + col];
            v.x += av.x; v.y += av.y; v.z += av.z; v.w += av.w;
        }
        if (GELU) {
            v.x = 0.5f * v.x * (1.f + erff(v.x * 0.70710678118654752f));
            v.y = 0.5f * v.y * (1.f + erff(v.y * 0.70710678118654752f));
            v.z = 0.5f * v.z * (1.f + erff(v.z * 0.70710678118654752f));
            v.w = 0.5f * v.w * (1.f + erff(v.w * 0.70710678118654752f));
        }
        *(float4*)&Co[row * N + col] = v;
    }
}

// ---------------------------------------------------------------------------
// LayerNorm: one block (256 threads) per row of 768.
// ---------------------------------------------------------------------------
__global__ void ln_kernel(const float* __restrict__ x,
                          const float* __restrict__ w,
                          const float* __restrict__ b,
                          float* __restrict__ o)
{
    __shared__ float red[16];
    const long row = blockIdx.x;
    const float* xr = x + row * CC;
    const int tid = threadIdx.x;
    const float v0 = xr[tid], v1 = xr[tid + 256], v2 = xr[tid + 512];
    float s = v0 + v1 + v2;
    float s2 = v0 * v0 + v1 * v1 + v2 * v2;
    #pragma unroll
    for (int off = 16; off; off >>= 1) {
        s  += __shfl_down_sync(0xffffffffu, s,  off);
        s2 += __shfl_down_sync(0xffffffffu, s2, off);
    }
    const int lane = tid & 31, wp = tid >> 5;
    if (!lane) { red[wp] = s; red[wp + 8] = s2; }
    __syncthreads();
    if (tid == 0) {
        float a = 0.f, a2 = 0.f;
        #pragma unroll
        for (int i = 0; i < 8; i++) { a += red[i]; a2 += red[i + 8]; }
        red[0] = a; red[8] = a2;
    }
    __syncthreads();
    const float mu = red[0] * (1.f / 768.f);
    const float var = red[8] * (1.f / 768.f) - mu * mu;
    const float rs = rsqrtf(var + 1e-5f);
    float* orow = o + row * CC;
    orow[tid]       = (v0 - mu) * rs * w[tid]       + b[tid];
    orow[tid + 256] = (v1 - mu) * rs * w[tid + 256] + b[tid + 256];
    orow[tid + 512] = (v2 - mu) * rs * w[tid + 512] + b[tid + 512];
}

// ---------------------------------------------------------------------------
// Tiled attention: one block per (64-query tile, head, batch). 256 threads.
// SMEM: full score strip S[64][768] + staged Q/K/V 64x64 tiles (stride 68,
// 16B-aligned for float4). Mask (j%256)<=(i%256) => key tile kt valid iff
// (kt&3) <= (qt&3); diagonal tile masked elementwise; fully-masked tiles
// skipped in all passes.
// ---------------------------------------------------------------------------
#define ATTN_SMEM_FLOATS (64*768 + 2*64*68 + 64)

__global__ void attn_tiled(const float* __restrict__ qkv, float* __restrict__ y)
{
    extern __shared__ float sm[];
    float* S    = sm;                 // [64][768]
    float* Qs   = sm + 64 * 768;      // [d][q] : [64][68]
    float* KVs  = Qs + 64 * 68;       // K pass: [d][k]; V pass: [k][d]
    float* rsum = KVs + 64 * 68;      // [64] reciprocal row sums

    const int qt = blockIdx.x, h = blockIdx.y, b = blockIdx.z;
    const int tid = threadIdx.x;
    const int tx = tid & 15, ty = tid >> 4;
    const int q0 = qt * 64;
    const int qm = qt & 3;
    const float* base = qkv + (long)b * TF * 3 * CC + h * 64;

    // Load Q tile (scaled by 1/sqrt(D)), stored transposed [d][q]
    for (int idx = tid; idx < 4096; idx += 256) {
        const int r = idx >> 6, d = idx & 63;
        Qs[d * 68 + r] = base[(long)(q0 + r) * 3 * CC + d] * 0.125f;
    }

    // ---- Pass 1: scores S = Q K^T over valid key tiles ----
    for (int seg = 0; seg < 3; seg++) {
        for (int m = 0; m <= qm; m++) {
            const int k0 = (seg * 4 + m) * 64;
            __syncthreads();
            for (int idx = tid; idx < 4096; idx += 256) {
                const int r = idx >> 6, d = idx & 63;
                KVs[d * 68 + r] = base[(long)(k0 + r) * 3 * CC + CC + d];
            }
            __syncthreads();
            float acc[4][4] = {};
            #pragma unroll 8
            for (int d = 0; d < 64; d++) {
                const float4 av = *(const float4*)&Qs[d * 68 + ty * 4];
                const float4 bv = *(const float4*)&KVs[d * 68 + tx * 4];
                const float a_[4] = {av.x, av.y, av.z, av.w};
                const float b_[4] = {bv.x, bv.y, bv.z, bv.w};
                #pragma unroll
                for (int i = 0; i < 4; i++)
                    #pragma unroll
                    for (int j = 0; j < 4; j++)
                        acc[i][j] = fmaf(a_[i], b_[j], acc[i][j]);
            }
            const bool diag = (m == qm);
            #pragma unroll
            for (int i = 0; i < 4; i++) {
                const int qq = ty * 4 + i;
                float4 v = make_float4(acc[i][0], acc[i][1], acc[i][2], acc[i][3]);
                if (diag) {
                    const int kk = tx * 4;
                    if (kk + 0 > qq) v.x = -1e30f;
                    if (kk + 1 > qq) v.y = -1e30f;
                    if (kk + 2 > qq) v.z = -1e30f;
                    if (kk + 3 > qq) v.w = -1e30f;
                }
                *(float4*)&S[qq * 768 + k0 + tx * 4] = v;
            }
        }
    }
    __syncthreads();

    // ---- Pass 2: softmax per row over valid tiles (warp per row) ----
    const int lane = tid & 31, wp = tid >> 5;
    for (int r = wp; r < 64; r += 8) {
        float mx = -1e30f;
        for (int seg = 0; seg < 3; seg++)
            for (int m = 0; m <= qm; m++) {
                const int c0 = (seg * 4 + m) * 64;
                mx = fmaxf(mx, fmaxf(S[r * 768 + c0 + lane],
                                     S[r * 768 + c0 + 32 + lane]));
            }
        #pragma unroll
        for (int off = 16; off; off >>= 1)
            mx = fmaxf(mx, __shfl_xor_sync(0xffffffffu, mx, off));
        float sum = 0.f;
        for (int seg = 0; seg < 3; seg++)
            for (int m = 0; m <= qm; m++) {
                const int c0 = (seg * 4 + m) * 64;
                const float p1 = __expf(S[r * 768 + c0 + lane] - mx);
                const float p2 = __expf(S[r * 768 + c0 + 32 + lane] - mx);
                S[r * 768 + c0 + lane] = p1;
                S[r * 768 + c0 + 32 + lane] = p2;
                sum += p1 + p2;
            }
        #pragma unroll
        for (int off = 16; off; off >>= 1)
            sum += __shfl_xor_sync(0xffffffffu, sum, off);
        if (!lane) rsum[r] = 1.f / sum;
    }
    __syncthreads();

    // ---- Pass 3: O = P V over valid tiles ----
    float o[4][4] = {};
    for (int seg = 0; seg < 3; seg++) {
        for (int m = 0; m <= qm; m++) {
            const int k0 = (seg * 4 + m) * 64;
            __syncthreads();
            for (int idx = tid; idx < 4096; idx += 256) {
                const int r = idx >> 6, d = idx & 63;
                KVs[r * 68 + d] = base[(long)(k0 + r) * 3 * CC + 2 * CC + d];
            }
            __syncthreads();
            for (int kk = 0; kk < 64; kk += 4) {
                float amat[4][4];
                #pragma unroll
                for (int i = 0; i < 4; i++) {
                    const float4 t = *(const float4*)&S[(ty * 4 + i) * 768 + k0 + kk];
                    amat[i][0] = t.x; amat[i][1] = t.y;
                    amat[i][2] = t.z; amat[i][3] = t.w;
                }
                #pragma unroll
                for (int u = 0; u < 4; u++) {
                    const float4 bv = *(const float4*)&KVs[(kk + u) * 68 + tx * 4];
                    #pragma unroll
                    for (int i = 0; i < 4; i++) {
                        o[i][0] = fmaf(amat[i][u], bv.x, o[i][0]);
                        o[i][1] = fmaf(amat[i][u], bv.y, o[i][1]);
                        o[i][2] = fmaf(amat[i][u], bv.z, o[i][2]);
                        o[i][3] = fmaf(amat[i][u], bv.w, o[i][3]);
                    }
                }
            }
        }
    }

    // ---- Write output ----
    float* yb = y + ((long)b * TF + q0) * CC + h * 64 + tx * 4;
    #pragma unroll
    for (int i = 0; i < 4; i++) {
        const int qq = ty * 4 + i;
        const float inv = rsum[qq];
        float4 v = make_float4(o[i][0] * inv, o[i][1] * inv,
                               o[i][2] * inv, o[i][3] * inv);
        *(float4*)&yb[(long)qq * CC] = v;
    }
}

// ---------------------------------------------------------------------------
// Token embedding segments (up/down) + positional emb.
// ---------------------------------------------------------------------------
__global__ void embed_tok(const int* __restrict__ iu, const int* __restrict__ idn,
                          const float* __restrict__ tu, const float* __restrict__ td,
                          const float* __restrict__ pos, float* __restrict__ x)
{
    const int gid = blockIdx.x * blockDim.x + threadIdx.x;
    const int total = 2 * BB * TT * CC;
    if (gid >= total) return;
    const int c = gid % CC;
    const int rr = gid / CC;
    const int i = rr % TT;
    const int bb = (rr / TT) % BB;
    const int seg = rr / (TT * BB);
    if (seg == 0)
        x[((long)bb * TF + TT + i) * CC + c] =
            tu[(long)iu[bb * TT + i] * CC + c] + pos[(TT + i) * CC + c];
    else
        x[((long)bb * TF + 2 * TT + i) * CC + c] =
            td[(long)idn[bb * TT + i] * CC + c] + pos[(2 * TT + i) * CC + c];
}

// ---------------------------------------------------------------------------
extern "C" void kernel_launch(void* const* d_in, const int* in_sizes, int n_in,
                              void* d_out, int out_size)
{
    (void)n_in; (void)out_size;
    const int*   idx_up   = (const int*)d_in[0];
    const int*   idx_down = (const int*)d_in[1];
    const float* cond     = (const float*)d_in[2];
    const float* tok_up   = (const float*)d_in[3];
    const float* tok_down = (const float*)d_in[4];
    const float* pos_emb  = (const float*)d_in[5];
    const float* cond_w   = (const float*)d_in[6];
    const float* cond_b   = (const float*)d_in[7];

    // dict order vs signature order (see R1 note); disambiguate on in_sizes[8]
    const bool dict_order = (in_sizes[8] == CC);

    const float* P[2][10];
    const float *lnf_w, *lnf_b, *head_up_w, *head_down_w;
    if (dict_order) {
        lnf_w       = (const float*)d_in[8];
        lnf_b       = (const float*)d_in[9];
        head_up_w   = (const float*)d_in[10];
        head_down_w = (const float*)d_in[11];
        for (int s = 0; s < 2; s++)
            for (int p = 0; p < 10; p++)
                P[s][p] = (const float*)d_in[12 + s * 10 + p];
    } else {
        for (int s = 0; s < 2; s++)
            for (int p = 0; p < 10; p++)
                P[s][p] = (const float*)d_in[8 + s * 10 + p];
        lnf_w       = (const float*)d_in[28];
        lnf_b       = (const float*)d_in[29];
        head_up_w   = (const float*)d_in[30];
        head_down_w = (const float*)d_in[31];
    }
    float* out = (float*)d_out;

    float *x, *h, *qkv, *y, *u;
    cudaGetSymbolAddress((void**)&x,   g_x);
    cudaGetSymbolAddress((void**)&h,   g_h);
    cudaGetSymbolAddress((void**)&qkv, g_qkv);
    cudaGetSymbolAddress((void**)&y,   g_y);
    cudaGetSymbolAddress((void**)&u,   g_u);

    const int NROW = BB * TF;   // 1536
    const int ATTN_SMEM = ATTN_SMEM_FLOATS * 4;   // 231,680 bytes
    cudaFuncSetAttribute(attn_tiled,
                         cudaFuncAttributeMaxDynamicSharedMemorySize, ATTN_SMEM);

    // Embedding
    gemm_k<false><<<dim3(CC / 64, TT / 64, BB), 256>>>(
        cond, (long)TT * MC, cond_w, cond_b, pos_emb, 0,
        x, (long)TF * CC, TT, CC, MC);
    embed_tok<<<(2 * BB * TT * CC + 255) / 256, 256>>>(
        idx_up, idx_down, tok_up, tok_down, pos_emb, x);

    for (int s = 0; s < 2; s++) {
        for (int l = 0; l < NLAYER; l++) {
            const float* ln1  = P[s][0] + (long)l * 2 * CC;
            const float* ln2  = P[s][1] + (long)l * 2 * CC;
            const float* qkvW = P[s][2] + (long)l * 3 * CC * CC;
            const float* qkvB = P[s][3] + (long)l * 3 * CC;
            const float* prjW = P[s][4] + (long)l * CC * CC;
            const float* prjB = P[s][5] + (long)l * CC;
            const float* f1W  = P[s][6] + (long)l * 4 * CC * CC;
            const float* f1B  = P[s][7] + (long)l * 4 * CC;
            const float* f2W  = P[s][8] + (long)l * CC * 4 * CC;
            const float* f2B  = P[s][9] + (long)l * CC;

            ln_kernel<<<NROW, 256>>>(x, ln1, ln1 + CC, h);
            gemm_k<false><<<dim3(3 * CC / 64, NROW / 64, 1), 256>>>(
                h, 0, qkvW, qkvB, nullptr, 0, qkv, 0, NROW, 3 * CC, CC);
            attn_tiled<<<dim3(TF / 64, HH, BB), 256, ATTN_SMEM>>>(qkv, y);
            gemm_k<false><<<dim3(CC / 64, NROW / 64, 1), 256>>>(
                y, 0, prjW, prjB, x, 0, x, 0, NROW, CC, CC);
            ln_kernel<<<NROW, 256>>>(x, ln2, ln2 + CC, h);
            gemm_k<true><<<dim3(4 * CC / 64, NROW / 64, 1), 256>>>(
                h, 0, f1W, f1B, nullptr, 0, u, 0, NROW, 4 * CC, CC);
            gemm_k<false><<<dim3(CC / 64, NROW / 64, 1), 256>>>(
                u, 0, f2W, f2B, x, 0, x, 0, NROW, CC, 4 * CC);
        }
    }

    // Final LN + heads
    ln_kernel<<<NROW, 256>>>(x, lnf_w, lnf_b, h);
    gemm_k<false><<<dim3(VV / 64, TT / 64, BB), 256>>>(
        h + (long)TT * CC, (long)TF * CC, head_up_w, nullptr, nullptr, 0,
        out, (long)TT * VV, TT, VV, CC);
    gemm_k<false><<<dim3(VV / 64, TT / 64, BB), 256>>>(
        h + (long)2 * TT * CC, (long)TF * CC, head_down_w, nullptr, nullptr, 0,
        out + (long)BB * TT * VV, (long)TT * VV, TT, VV, CC);
}